// round 8
// baseline (speedup 1.0000x reference)
#include <cuda_runtime.h>
#include <cstdint>

typedef unsigned long long ull;

#define Bb 256
#define Ss 365
#define FDd 32
#define FSs 27
#define Hh 256
#define KK 288              // 32 (x) + 256 (h) combined reduction dim
#define KP 144              // k-pairs
#define NTHR 512
#define NW 16
#define OFF_H 93440         // out: [B*S] floats first
#define OFF_C 24014080      // then h_n [B,S,H], then c_n [B,S,H]

// smem layout (bytes)
#define SMEM_WSM 0                       // [3][144 kp][32 j][2] f32 = 110592
#define SMEM_HP  110592                  // [8 bpairs][288 k] f32x2 = 18432
#define SMEM_PART 129024                 // [16 ksplit][8 bp][3 g][32 j] f32x2 = 98304
#define SMEM_TOTAL 227328

__device__ __forceinline__ ull dupf(float x) {
    ull d; asm("mov.b64 %0, {%1, %1};" : "=l"(d) : "f"(x)); return d;
}
__device__ __forceinline__ ull packf(float lo, float hi) {
    ull d; asm("mov.b64 %0, {%1, %2};" : "=l"(d) : "f"(lo), "f"(hi)); return d;
}
__device__ __forceinline__ void unpackf(ull v, float& lo, float& hi) {
    asm("mov.b64 {%0, %1}, %2;" : "=f"(lo), "=f"(hi) : "l"(v));
}
__device__ __forceinline__ void unpack_dup(ull v, ull& d0, ull& d1) {
    float lo, hi;
    asm("mov.b64 {%0, %1}, %2;" : "=f"(lo), "=f"(hi) : "l"(v));
    d0 = dupf(lo);
    d1 = dupf(hi);
}
__device__ __forceinline__ void fma2(ull& d, ull a, ull b) {
    asm("fma.rn.f32x2 %0, %1, %2, %0;" : "+l"(d) : "l"(a), "l"(b));
}
__device__ __forceinline__ ull add2(ull a, ull b) {
    ull d; asm("add.rn.f32x2 %0, %1, %2;" : "=l"(d) : "l"(a), "l"(b)); return d;
}
__device__ __forceinline__ float sigm(float x) {
    x = fminf(fmaxf(x, -30.f), 30.f);
    return __fdividef(1.f, 1.f + __expf(-x));
}
__device__ __forceinline__ float tanh_(float x) {
    float ax = fminf(fabsf(x), 15.f);
    float e = __expf(2.f * ax);
    float r = 1.f - __fdividef(2.f, e + 1.f);
    return copysignf(r, x);
}

__global__ void __cluster_dims__(8, 1, 1) __launch_bounds__(NTHR, 1)
ealstm_main(const float* __restrict__ x_d, const float* __restrict__ x_s,
            const float* __restrict__ W_ih, const float* __restrict__ W_hh,
            const float* __restrict__ W_sh, const float* __restrict__ bias,
            const float* __restrict__ bias_s, float* __restrict__ out)
{
    extern __shared__ char smem[];
    float* wsm  = (float*)(smem + SMEM_WSM);
    ull*   wsmq = (ull*)  (smem + SMEM_WSM);     // [3][144][32] ull view (k-pairs)
    ull*   hp2  = (ull*)  (smem + SMEM_HP);      // [8][288] ull
    const ulonglong2* hv2 = (const ulonglong2*)(smem + SMEM_HP);  // [8][144]
    ull*   part = (ull*)  (smem + SMEM_PART);

    const int tid = threadIdx.x;
    const int cl  = blockIdx.x >> 3;     // 16 clusters
    const int rk  = blockIdx.x & 7;      // rank in cluster
    const int b0  = cl * 16;             // 16 batch rows per cluster
    const int h0  = rk * 32;             // 32 hidden cols per CTA
    const int w   = tid >> 5;            // warp 0..15 = k-split id
    const int lane = tid & 31;           // = j within slice
    const int bp_st = w & 7;             // staging: bpair this warp fills
    const int half  = w >> 3;            // staging: which half of h (k quads)

    // ---- prologue: stage [W_ih;W_hh] slice into smem, k-pair interleaved ----
    // wsm[((g*144 + (k>>1))*32 + j)*2 + (k&1)] = W[k][g*256 + h0 + j]
    for (int idx = tid; idx < 3 * KK * 32; idx += NTHR) {
        int g = idx / (KK * 32);
        int r = idx - g * KK * 32;
        int k = r >> 5;
        int j = r & 31;
        int col = g * 256 + h0 + j;
        float v = (k < 32) ? W_ih[k * 768 + col] : W_hh[(k - 32) * 768 + col];
        wsm[((g * KP + (k >> 1)) * 32 + j) * 2 + (k & 1)] = v;
    }

    // elementwise state lives in warps 0-7: thread (w, lane) owns rows
    // (b0+w, b0+w+8), col h0+lane
    const int jg = h0 + lane;
    const int bglo = b0 + bp_st, bghi = bglo + 8;   // also used for staging
    float igv[2], cst[2] = {0.f, 0.f};
    ull bfd = 0, bod = 0, bgd = 0;
    float xplo = 0.f, xphi = 0.f;
    if (w < 8) {
        #pragma unroll
        for (int e = 0; e < 2; e++) {
            int b = b0 + w + 8 * e;
            float a = bias_s[jg];
            #pragma unroll
            for (int k = 0; k < FSs; k++)
                a = fmaf(x_s[b * FSs + k], W_sh[k * Hh + jg], a);
            igv[e] = sigm(a);
        }
        bfd = dupf(bias[jg]);
        bod = dupf(bias[256 + jg]);
        bgd = dupf(bias[512 + jg]);
        // x prefetch for t=0 (x rows are DRAM-cold; keep off the critical path)
        xplo = x_d[(bglo * Ss + 0) * FDd + lane];
        xphi = x_d[(bghi * Ss + 0) * FDd + lane];
    }

    for (int t = 0; t < Ss; t++) {
        // ---- stage [x_t | h_{t-1}]: warp pair (w, w+8) fills bpair bp_st ----
        if (w < 8)
            hp2[bp_st * KK + lane] = packf(xplo, xphi);
        if (t > 0) {
            const float4* plo = (const float4*)&out[OFF_H + (bglo * Ss + (t - 1)) * Hh];
            const float4* phi = (const float4*)&out[OFF_H + (bghi * Ss + (t - 1)) * Hh];
            int kq = half * 32 + lane;                  // quad index 0..63
            float4 lo4 = __ldcg(&plo[kq]);
            float4 hi4 = __ldcg(&phi[kq]);
            ulonglong2* dst = (ulonglong2*)&hp2[bp_st * KK + 32 + kq * 4];
            dst[0] = make_ulonglong2(packf(lo4.x, hi4.x), packf(lo4.y, hi4.y));
            dst[1] = make_ulonglong2(packf(lo4.z, hi4.z), packf(lo4.w, hi4.w));
        } else {
            int kq = half * 32 + lane;
            ulonglong2* dst = (ulonglong2*)&hp2[bp_st * KK + 32 + kq * 4];
            dst[0] = make_ulonglong2(0ull, 0ull);
            dst[1] = make_ulonglong2(0ull, 0ull);
        }
        // prefetch next step's x (consumed after next cluster barrier -> hidden)
        if (w < 8 && t + 1 < Ss) {
            xplo = x_d[(bglo * Ss + t + 1) * FDd + lane];
            xphi = x_d[(bghi * Ss + t + 1) * FDd + lane];
        }
        __syncthreads();

        // ---- GEMM: warp w does k-pairs [w*9, w*9+9) for all 8 bpairs ----
        ull acc[24];
        #pragma unroll
        for (int i = 0; i < 24; i++) acc[i] = 0ull;
        const int kp0 = w * 9;
        #pragma unroll
        for (int i = 0; i < 9; i++) {
            const int kp = kp0 + i;
            ull wf2 = wsmq[(0 * KP + kp) * 32 + lane];
            ull wo2 = wsmq[(1 * KP + kp) * 32 + lane];
            ull wg2 = wsmq[(2 * KP + kp) * 32 + lane];
            ull wfd0, wfd1, wod0, wod1, wgd0, wgd1;
            unpack_dup(wf2, wfd0, wfd1);
            unpack_dup(wo2, wod0, wod1);
            unpack_dup(wg2, wgd0, wgd1);
            #pragma unroll
            for (int bp = 0; bp < 8; bp++) {
                ulonglong2 h2 = hv2[bp * KP + kp];       // broadcast LDS.128
                fma2(acc[bp * 3 + 0], h2.x, wfd0);
                fma2(acc[bp * 3 + 1], h2.x, wod0);
                fma2(acc[bp * 3 + 2], h2.x, wgd0);
                fma2(acc[bp * 3 + 0], h2.y, wfd1);
                fma2(acc[bp * 3 + 1], h2.y, wod1);
                fma2(acc[bp * 3 + 2], h2.y, wgd1);
            }
        }
        #pragma unroll
        for (int bp = 0; bp < 8; bp++)
            #pragma unroll
            for (int g = 0; g < 3; g++)
                part[((w * 8 + bp) * 3 + g) * 32 + lane] = acc[bp * 3 + g];
        __syncthreads();

        // ---- warps 0-7: reduce 16 K-splits + bias, elementwise, store h/c ----
        if (w < 8) {
            ull sf = bfd, so = bod, sg = bgd;
            #pragma unroll
            for (int wk = 0; wk < NW; wk++) {
                sf = add2(sf, part[((wk * 8 + w) * 3 + 0) * 32 + lane]);
                so = add2(so, part[((wk * 8 + w) * 3 + 1) * 32 + lane]);
                sg = add2(sg, part[((wk * 8 + w) * 3 + 2) * 32 + lane]);
            }
            float f0, f1, o0, o1, g0, g1;
            unpackf(sf, f0, f1);
            unpackf(so, o0, o1);
            unpackf(sg, g0, g1);

            {
                cst[0] = sigm(f0) * cst[0] + igv[0] * tanh_(g0);
                float hv = sigm(o0) * tanh_(cst[0]);
                int base = ((b0 + w) * Ss + t) * Hh + jg;
                out[OFF_H + base] = hv;
                out[OFF_C + base] = cst[0];
            }
            {
                cst[1] = sigm(f1) * cst[1] + igv[1] * tanh_(g1);
                float hv = sigm(o1) * tanh_(cst[1]);
                int base = ((b0 + w + 8) * Ss + t) * Hh + jg;
                out[OFF_H + base] = hv;
                out[OFF_C + base] = cst[1];
            }
        }

        // cluster barrier: release our h[t] stores / acquire peers' before next stage
        asm volatile("barrier.cluster.arrive.aligned;" ::: "memory");
        asm volatile("barrier.cluster.wait.aligned;" ::: "memory");
    }
}

__global__ void __launch_bounds__(256)
fc_head(const float* __restrict__ h, const float* __restrict__ W_fc,
        const float* __restrict__ b_fc, float* __restrict__ outp)
{
    int row = blockIdx.x * 8 + (threadIdx.x >> 5);
    int lane = threadIdx.x & 31;
    if (row >= Bb * Ss) return;
    const float* hr = h + (size_t)row * Hh;
    float a = 0.f;
    #pragma unroll
    for (int i = 0; i < 8; i++)
        a = fmaf(hr[lane + 32 * i], W_fc[lane + 32 * i], a);
    #pragma unroll
    for (int s2 = 16; s2; s2 >>= 1)
        a += __shfl_xor_sync(0xffffffffu, a, s2);
    if (lane == 0) outp[row] = a + b_fc[0];
}

extern "C" void kernel_launch(void* const* d_in, const int* in_sizes, int n_in,
                              void* d_out, int out_size) {
    const float* x_d    = (const float*)d_in[0];
    const float* x_s    = (const float*)d_in[1];
    const float* W_ih   = (const float*)d_in[2];
    const float* W_hh   = (const float*)d_in[3];
    const float* W_sh   = (const float*)d_in[4];
    const float* bias   = (const float*)d_in[5];
    const float* bias_s = (const float*)d_in[6];
    const float* W_fc   = (const float*)d_in[7];
    const float* b_fc   = (const float*)d_in[8];
    float* out = (float*)d_out;

    cudaFuncSetAttribute(ealstm_main, cudaFuncAttributeMaxDynamicSharedMemorySize, SMEM_TOTAL);
    ealstm_main<<<128, NTHR, SMEM_TOTAL>>>(x_d, x_s, W_ih, W_hh, W_sh, bias, bias_s, out);
    fc_head<<<(Bb * Ss + 7) / 8, 256>>>(out + OFF_H, W_fc, b_fc, out);
}

// round 9
// speedup vs baseline: 1.1311x; 1.1311x over previous
#include <cuda_runtime.h>
#include <cstdint>

typedef unsigned long long ull;

#define Bb 256
#define Ss 365
#define FDd 32
#define FSs 27
#define Hh 256
#define KK 288              // 32 (x) + 256 (h) combined reduction dim
#define KP 144              // k-pairs
#define NTHR 256
#define OFF_H 93440         // out: [B*S] floats first
#define OFF_C 24014080      // then h_n [B,S,H], then c_n [B,S,H]

// smem layout (bytes)
#define SMEM_WSM 0                       // [3][144 kp][32 j][2] f32 = 110592
#define SMEM_HP  110592                  // [8 bpairs][288 k] f32x2 = 18432
#define SMEM_PART 129024                 // [8 ksplit][8 bp][3 g][32 j] f32x2 = 49152
#define SMEM_TOTAL 178176

__device__ __forceinline__ ull dupf(float x) {
    ull d; asm("mov.b64 %0, {%1, %1};" : "=l"(d) : "f"(x)); return d;
}
__device__ __forceinline__ ull packf(float lo, float hi) {
    ull d; asm("mov.b64 %0, {%1, %2};" : "=l"(d) : "f"(lo), "f"(hi)); return d;
}
__device__ __forceinline__ void unpackf(ull v, float& lo, float& hi) {
    asm("mov.b64 {%0, %1}, %2;" : "=f"(lo), "=f"(hi) : "l"(v));
}
__device__ __forceinline__ void unpack_dup(ull v, ull& d0, ull& d1) {
    float lo, hi;
    asm("mov.b64 {%0, %1}, %2;" : "=f"(lo), "=f"(hi) : "l"(v));
    d0 = dupf(lo);
    d1 = dupf(hi);
}
__device__ __forceinline__ void fma2(ull& d, ull a, ull b) {
    asm("fma.rn.f32x2 %0, %1, %2, %0;" : "+l"(d) : "l"(a), "l"(b));
}
__device__ __forceinline__ ull add2(ull a, ull b) {
    ull d; asm("add.rn.f32x2 %0, %1, %2;" : "=l"(d) : "l"(a), "l"(b)); return d;
}
__device__ __forceinline__ float sigm(float x) {
    x = fminf(fmaxf(x, -30.f), 30.f);
    return __fdividef(1.f, 1.f + __expf(-x));
}
__device__ __forceinline__ float tanh_(float x) {
    float ax = fminf(fabsf(x), 15.f);
    float e = __expf(2.f * ax);
    float r = 1.f - __fdividef(2.f, e + 1.f);
    return copysignf(r, x);
}

__global__ void __cluster_dims__(8, 1, 1) __launch_bounds__(NTHR, 1)
ealstm_seg(const float* __restrict__ x_d, const float* __restrict__ x_s,
           const float* __restrict__ W_ih, const float* __restrict__ W_hh,
           const float* __restrict__ W_sh, const float* __restrict__ bias,
           const float* __restrict__ bias_s, float* __restrict__ out,
           int t0, int t1)
{
    extern __shared__ char smem[];
    float* wsm  = (float*)(smem + SMEM_WSM);
    ull*   wsmq = (ull*)  (smem + SMEM_WSM);     // [3][144][32] ull view (k-pairs)
    ull*   hp2  = (ull*)  (smem + SMEM_HP);      // [8][288] ull
    const ulonglong2* hv2 = (const ulonglong2*)(smem + SMEM_HP);  // [8][144]
    ull*   part = (ull*)  (smem + SMEM_PART);

    const int tid = threadIdx.x;
    const int cl  = blockIdx.x >> 3;     // 16 clusters
    const int rk  = blockIdx.x & 7;      // rank in cluster
    const int b0  = cl * 16;             // 16 batch rows per cluster
    const int h0  = rk * 32;             // 32 hidden cols per CTA
    const int w   = tid >> 5;            // warp 0..7 = bpair id = k-split id
    const int lane = tid & 31;           // = j within slice

    // ---- prologue: stage [W_ih;W_hh] slice into smem, k-pair interleaved ----
    // wsm[((g*144 + (k>>1))*32 + j)*2 + (k&1)] = W[k][g*256 + h0 + j]
    for (int idx = tid; idx < 3 * KK * 32; idx += NTHR) {
        int g = idx / (KK * 32);
        int r = idx - g * KK * 32;
        int k = r >> 5;
        int j = r & 31;
        int col = g * 256 + h0 + j;
        float v = (k < 32) ? W_ih[k * 768 + col] : W_hh[(k - 32) * 768 + col];
        wsm[((g * KP + (k >> 1)) * 32 + j) * 2 + (k & 1)] = v;
    }

    // static input gate: thread (w, lane) owns rows (b0+w, b0+w+8), col h0+lane
    const int jg = h0 + lane;
    const int bglo = b0 + w, bghi = bglo + 8;
    float igv[2], cst[2];
    #pragma unroll
    for (int e = 0; e < 2; e++) {
        int b = b0 + w + 8 * e;
        float a = bias_s[jg];
        #pragma unroll
        for (int k = 0; k < FSs; k++)
            a = fmaf(x_s[b * FSs + k], W_sh[k * Hh + jg], a);
        igv[e] = sigm(a);
        // resume cell state: exact value stored by the previous segment
        cst[e] = (t0 == 0) ? 0.f
                           : __ldcg(&out[OFF_C + (b * Ss + (t0 - 1)) * Hh + jg]);
    }
    const ull bfd = dupf(bias[jg]);
    const ull bod = dupf(bias[256 + jg]);
    const ull bgd = dupf(bias[512 + jg]);

    // x prefetch for t0 (x rows are DRAM/L2-cold; keep off the critical path)
    float xplo = x_d[(bglo * Ss + t0) * FDd + lane];
    float xphi = x_d[(bghi * Ss + t0) * FDd + lane];

    for (int t = t0; t < t1; t++) {
        // ---- stage [x_t | h_{t-1}]: warp w fills bpair w ----
        hp2[w * KK + lane] = packf(xplo, xphi);
        if (t > 0) {
            const float4* plo = (const float4*)&out[OFF_H + (bglo * Ss + (t - 1)) * Hh];
            const float4* phi = (const float4*)&out[OFF_H + (bghi * Ss + (t - 1)) * Hh];
            #pragma unroll
            for (int i = 0; i < 2; i++) {
                int kq = i * 32 + lane;                  // quad index 0..63
                float4 lo4 = __ldcg(&plo[kq]);
                float4 hi4 = __ldcg(&phi[kq]);
                ulonglong2* dst = (ulonglong2*)&hp2[w * KK + 32 + kq * 4];
                dst[0] = make_ulonglong2(packf(lo4.x, hi4.x), packf(lo4.y, hi4.y));
                dst[1] = make_ulonglong2(packf(lo4.z, hi4.z), packf(lo4.w, hi4.w));
            }
        } else {
            #pragma unroll
            for (int i = 0; i < 8; i++) hp2[w * KK + 32 + i * 32 + lane] = 0ull;
        }
        // prefetch next step's x (consumed after next cluster barrier -> hidden)
        if (t + 1 < t1) {
            xplo = x_d[(bglo * Ss + t + 1) * FDd + lane];
            xphi = x_d[(bghi * Ss + t + 1) * FDd + lane];
        }
        __syncthreads();

        // ---- GEMM: warp w does k-pairs [w*18, w*18+18) for all 8 bpairs ----
        ull acc[24];
        #pragma unroll
        for (int i = 0; i < 24; i++) acc[i] = 0ull;
        const int kp0 = w * 18;
        #pragma unroll
        for (int i = 0; i < 18; i++) {
            const int kp = kp0 + i;
            ull wf2 = wsmq[(0 * KP + kp) * 32 + lane];
            ull wo2 = wsmq[(1 * KP + kp) * 32 + lane];
            ull wg2 = wsmq[(2 * KP + kp) * 32 + lane];
            ull wfd0, wfd1, wod0, wod1, wgd0, wgd1;
            unpack_dup(wf2, wfd0, wfd1);
            unpack_dup(wo2, wod0, wod1);
            unpack_dup(wg2, wgd0, wgd1);
            #pragma unroll
            for (int bp = 0; bp < 8; bp++) {
                ulonglong2 h2 = hv2[bp * KP + kp];       // broadcast LDS.128
                fma2(acc[bp * 3 + 0], h2.x, wfd0);
                fma2(acc[bp * 3 + 1], h2.x, wod0);
                fma2(acc[bp * 3 + 2], h2.x, wgd0);
                fma2(acc[bp * 3 + 0], h2.y, wfd1);
                fma2(acc[bp * 3 + 1], h2.y, wod1);
                fma2(acc[bp * 3 + 2], h2.y, wgd1);
            }
        }
        #pragma unroll
        for (int bp = 0; bp < 8; bp++)
            #pragma unroll
            for (int g = 0; g < 3; g++)
                part[((w * 8 + bp) * 3 + g) * 32 + lane] = acc[bp * 3 + g];
        __syncthreads();

        // ---- reduce K-splits + bias, elementwise update, store h/c ----
        ull sf = bfd, so = bod, sg = bgd;
        #pragma unroll
        for (int wk = 0; wk < 8; wk++) {
            sf = add2(sf, part[((wk * 8 + w) * 3 + 0) * 32 + lane]);
            so = add2(so, part[((wk * 8 + w) * 3 + 1) * 32 + lane]);
            sg = add2(sg, part[((wk * 8 + w) * 3 + 2) * 32 + lane]);
        }
        float f0, f1, o0, o1, g0, g1;
        unpackf(sf, f0, f1);
        unpackf(so, o0, o1);
        unpackf(sg, g0, g1);

        {
            cst[0] = sigm(f0) * cst[0] + igv[0] * tanh_(g0);
            float hv = sigm(o0) * tanh_(cst[0]);
            int base = (bglo * Ss + t) * Hh + jg;
            __stcg(&out[OFF_H + base], hv);
            __stcg(&out[OFF_C + base], cst[0]);
        }
        {
            cst[1] = sigm(f1) * cst[1] + igv[1] * tanh_(g1);
            float hv = sigm(o1) * tanh_(cst[1]);
            int base = (bghi * Ss + t) * Hh + jg;
            __stcg(&out[OFF_H + base], hv);
            __stcg(&out[OFF_C + base], cst[1]);
        }

        // cluster barrier: release our h[t] stores / acquire peers' before next stage
        asm volatile("barrier.cluster.arrive.aligned;" ::: "memory");
        asm volatile("barrier.cluster.wait.aligned;" ::: "memory");
    }
}

__global__ void __launch_bounds__(256)
fc_head(const float* __restrict__ h, const float* __restrict__ W_fc,
        const float* __restrict__ b_fc, float* __restrict__ outp)
{
    int row = blockIdx.x * 8 + (threadIdx.x >> 5);
    int lane = threadIdx.x & 31;
    if (row >= Bb * Ss) return;
    const float* hr = h + (size_t)row * Hh;
    float a = 0.f;
    #pragma unroll
    for (int i = 0; i < 8; i++)
        a = fmaf(hr[lane + 32 * i], W_fc[lane + 32 * i], a);
    #pragma unroll
    for (int s2 = 16; s2; s2 >>= 1)
        a += __shfl_xor_sync(0xffffffffu, a, s2);
    if (lane == 0) outp[row] = a + b_fc[0];
}

extern "C" void kernel_launch(void* const* d_in, const int* in_sizes, int n_in,
                              void* d_out, int out_size) {
    const float* x_d    = (const float*)d_in[0];
    const float* x_s    = (const float*)d_in[1];
    const float* W_ih   = (const float*)d_in[2];
    const float* W_hh   = (const float*)d_in[3];
    const float* W_sh   = (const float*)d_in[4];
    const float* bias   = (const float*)d_in[5];
    const float* bias_s = (const float*)d_in[6];
    const float* W_fc   = (const float*)d_in[7];
    const float* b_fc   = (const float*)d_in[8];
    float* out = (float*)d_out;

    cudaFuncSetAttribute(ealstm_seg, cudaFuncAttributeMaxDynamicSharedMemorySize, SMEM_TOTAL);
    // 3 segments so the ncu capture (-s 5) lands on a steady-state main segment
    ealstm_seg<<<128, NTHR, SMEM_TOTAL>>>(x_d, x_s, W_ih, W_hh, W_sh, bias, bias_s, out, 0, 122);
    ealstm_seg<<<128, NTHR, SMEM_TOTAL>>>(x_d, x_s, W_ih, W_hh, W_sh, bias, bias_s, out, 122, 244);
    ealstm_seg<<<128, NTHR, SMEM_TOTAL>>>(x_d, x_s, W_ih, W_hh, W_sh, bias, bias_s, out, 244, 365);
    fc_head<<<(Bb * Ss + 7) / 8, 256>>>(out + OFF_H, W_fc, b_fc, out);
}